// round 3
// baseline (speedup 1.0000x reference)
#include <cuda_runtime.h>

#define N_NODES 100000
#define N_EDGES 1600000
#define DIM 64
#define EPS 1e-5f
#define SCAN_B 512
#define ASTRIDE 68   // padded row length (floats) for k-major A tile; %4==0 for LDS.128

typedef unsigned long long ull;

// ---- scratch (device globals; no allocation allowed) ----
__device__ __align__(16) float g_h2[N_NODES * DIM];    // post-GEMM activations
__device__ int   g_deg_out[N_NODES];
__device__ int   g_deg_in[N_NODES];
__device__ int   g_off[N_NODES];      // CSR row offsets
__device__ int   g_fill[N_NODES];     // fill cursors
__device__ int   g_csr[N_EDGES];      // src indices grouped by dst
__device__ int   g_bsum[SCAN_B];
__device__ int   g_boff[SCAN_B];
__device__ float g_norm_src[N_NODES];
__device__ float g_sum[DIM];
__device__ float g_sumsq[DIM];
__device__ float g_scale[DIM];
__device__ float g_shift[DIM];

__device__ __forceinline__ void ffma2(ull& d, ull a, ull b) {
    asm("fma.rn.f32x2 %0, %1, %2, %0;" : "+l"(d) : "l"(a), "l"(b));
}
__device__ __forceinline__ float2 unpack2(ull v) {
    float2 r;
    asm("mov.b64 {%0, %1}, %2;" : "=f"(r.x), "=f"(r.y) : "l"(v));
    return r;
}

// ---------------------------------------------------------------------------
// 1) degree histogram (both directions), 4 edges per thread via int4
// ---------------------------------------------------------------------------
__global__ void deg_kernel(const int4* __restrict__ src4,
                           const int4* __restrict__ dst4, int e4) {
    int i = blockIdx.x * blockDim.x + threadIdx.x;
    if (i < e4) {
        int4 s = __ldg(src4 + i);
        int4 d = __ldg(dst4 + i);
        atomicAdd(&g_deg_out[s.x], 1); atomicAdd(&g_deg_out[s.y], 1);
        atomicAdd(&g_deg_out[s.z], 1); atomicAdd(&g_deg_out[s.w], 1);
        atomicAdd(&g_deg_in[d.x], 1);  atomicAdd(&g_deg_in[d.y], 1);
        atomicAdd(&g_deg_in[d.z], 1);  atomicAdd(&g_deg_in[d.w], 1);
    }
}

// ---------------------------------------------------------------------------
// 2a) per-block exclusive scan of deg_in
// ---------------------------------------------------------------------------
__global__ void scanA_kernel(int n) {
    __shared__ int sm[SCAN_B];
    int t = threadIdx.x;
    int i = blockIdx.x * SCAN_B + t;
    int v = (i < n) ? g_deg_in[i] : 0;
    sm[t] = v;
    __syncthreads();
    #pragma unroll
    for (int off = 1; off < SCAN_B; off <<= 1) {
        int a = (t >= off) ? sm[t - off] : 0;
        __syncthreads();
        sm[t] += a;
        __syncthreads();
    }
    if (i < n) g_off[i] = sm[t] - v;
    if (t == SCAN_B - 1) g_bsum[blockIdx.x] = sm[t];
}

// ---------------------------------------------------------------------------
// 2b) scan of block sums (single block); also zero BN accumulators
// ---------------------------------------------------------------------------
__global__ void scanB_kernel(int nb) {
    __shared__ int sm[SCAN_B];
    int t = threadIdx.x;
    int v = (t < nb) ? g_bsum[t] : 0;
    sm[t] = v;
    __syncthreads();
    #pragma unroll
    for (int off = 1; off < SCAN_B; off <<= 1) {
        int a = (t >= off) ? sm[t - off] : 0;
        __syncthreads();
        sm[t] += a;
        __syncthreads();
    }
    if (t < nb) g_boff[t] = sm[t] - v;
    if (t < DIM) { g_sum[t] = 0.f; g_sumsq[t] = 0.f; }
}

// ---------------------------------------------------------------------------
// 2c) finalize offsets + fill cursors + norm_src
// ---------------------------------------------------------------------------
__global__ void scanC_kernel(int n) {
    int i = blockIdx.x * blockDim.x + threadIdx.x;
    if (i < n) {
        int off = g_off[i] + g_boff[i >> 9];
        g_off[i] = off;
        g_fill[i] = off;
        int d = g_deg_out[i];
        g_norm_src[i] = rsqrtf((float)(d < 1 ? 1 : d));
    }
}

// ---------------------------------------------------------------------------
// 3) CSR bucket fill: group src indices by dst (4 edges/thread)
// ---------------------------------------------------------------------------
__global__ void fill_kernel(const int4* __restrict__ src4,
                            const int4* __restrict__ dst4, int e4) {
    int i = blockIdx.x * blockDim.x + threadIdx.x;
    if (i < e4) {
        int4 s = __ldg(src4 + i);
        int4 d = __ldg(dst4 + i);
        g_csr[atomicAdd(&g_fill[d.x], 1)] = s.x;
        g_csr[atomicAdd(&g_fill[d.y], 1)] = s.y;
        g_csr[atomicAdd(&g_fill[d.z], 1)] = s.z;
        g_csr[atomicAdd(&g_fill[d.w], 1)] = s.w;
    }
}

// ---------------------------------------------------------------------------
// 4) FUSED gather + GEMM + BN-stats.
//    Block = 64 nodes, 256 threads.
//    Phase A: gather agg rows directly into k-major smem tile.
//    Phase B: h2 = A @ W + b via f32x2 packed FMA; BN sum/sumsq fused.
// ---------------------------------------------------------------------------
__global__ void __launch_bounds__(256)
fused_kernel(const float4* __restrict__ x4,
             const float* __restrict__ W,
             const float* __restrict__ b, int n) {
    extern __shared__ char smraw[];
    ull*   Wdup = (ull*)smraw;                       // [DIM][DIM] f32x2 {w,w}  32KB
    float* Asm2 = (float*)(smraw + DIM * DIM * 8);   // [DIM k][ASTRIDE rows]  17.4KB
    float* cs   = (float*)(smraw + DIM * DIM * 8 + DIM * ASTRIDE * 4);
    float* css  = cs + DIM;

    int tid = threadIdx.x;
    int r0 = blockIdx.x * 64;

    // build duplicated-W table: Wdup[k*64+c] = {W[k][c], W[k][c]}
    #pragma unroll
    for (int j = 0; j < 16; j++) {
        int i = tid + j * 256;
        float w = __ldg(W + i);
        ((float2*)Wdup)[i] = make_float2(w, w);
    }
    if (tid < DIM) { cs[tid] = 0.f; css[tid] = 0.f; }

    // Phase A: gather. 16 lanes per node, 16 nodes per pass, 4 passes.
    int c = tid & 15;
    #pragma unroll
    for (int pass = 0; pass < 4; pass++) {
        int rloc = pass * 16 + (tid >> 4);
        int row = r0 + rloc;
        float4 acc = make_float4(0.f, 0.f, 0.f, 0.f);
        if (row < n) {
            int start = __ldg(&g_off[row]);
            int deg = __ldg(&g_deg_in[row]);
            int j = 0;
            for (; j + 1 < deg; j += 2) {
                int s0 = __ldg(&g_csr[start + j]);
                int s1 = __ldg(&g_csr[start + j + 1]);
                float ns0 = __ldg(&g_norm_src[s0]);
                float ns1 = __ldg(&g_norm_src[s1]);
                float4 v0 = __ldg(x4 + (size_t)s0 * 16 + c);
                float4 v1 = __ldg(x4 + (size_t)s1 * 16 + c);
                acc.x += ns0 * v0.x + ns1 * v1.x;
                acc.y += ns0 * v0.y + ns1 * v1.y;
                acc.z += ns0 * v0.z + ns1 * v1.z;
                acc.w += ns0 * v0.w + ns1 * v1.w;
            }
            if (j < deg) {
                int s = __ldg(&g_csr[start + j]);
                float ns = __ldg(&g_norm_src[s]);
                float4 v = __ldg(x4 + (size_t)s * 16 + c);
                acc.x += ns * v.x; acc.y += ns * v.y;
                acc.z += ns * v.z; acc.w += ns * v.w;
            }
            float nd = rsqrtf((float)(deg < 1 ? 1 : deg));
            acc.x *= nd; acc.y *= nd; acc.z *= nd; acc.w *= nd;
        }
        // k-major store: Asm2[(4c+j)*ASTRIDE + rloc]
        Asm2[(4 * c + 0) * ASTRIDE + rloc] = acc.x;
        Asm2[(4 * c + 1) * ASTRIDE + rloc] = acc.y;
        Asm2[(4 * c + 2) * ASTRIDE + rloc] = acc.z;
        Asm2[(4 * c + 3) * ASTRIDE + rloc] = acc.w;
    }
    __syncthreads();

    // Phase B: GEMM. thread (tx,ty): rows ty*4..+3, cols tx*4..+3.
    int tx = tid & 15;
    int ty = tid >> 4;
    ull acc2[2][4] = {};   // [row-pair][col], f32x2 packs rows (2p, 2p+1)

    #pragma unroll 4
    for (int k = 0; k < DIM; k++) {
        ulonglong2 av = *(const ulonglong2*)&Asm2[k * ASTRIDE + ty * 4]; // {a0,a1},{a2,a3}
        ulonglong2 wA = *(const ulonglong2*)&Wdup[k * DIM + tx * 4];     // cols 0,1
        ulonglong2 wB = *(const ulonglong2*)&Wdup[k * DIM + tx * 4 + 2]; // cols 2,3
        ffma2(acc2[0][0], av.x, wA.x); ffma2(acc2[1][0], av.y, wA.x);
        ffma2(acc2[0][1], av.x, wA.y); ffma2(acc2[1][1], av.y, wA.y);
        ffma2(acc2[0][2], av.x, wB.x); ffma2(acc2[1][2], av.y, wB.x);
        ffma2(acc2[0][3], av.x, wB.y); ffma2(acc2[1][3], av.y, wB.y);
    }

    float4 bv = ((const float4*)b)[tx];
    float ps[4] = {0.f, 0.f, 0.f, 0.f};
    float pss[4] = {0.f, 0.f, 0.f, 0.f};
    #pragma unroll
    for (int i = 0; i < 4; i++) {
        int gr = r0 + ty * 4 + i;
        if (gr < n) {
            int p = i >> 1, hi = i & 1;
            float2 u0 = unpack2(acc2[p][0]);
            float2 u1 = unpack2(acc2[p][1]);
            float2 u2 = unpack2(acc2[p][2]);
            float2 u3 = unpack2(acc2[p][3]);
            float4 o;
            o.x = (hi ? u0.y : u0.x) + bv.x;
            o.y = (hi ? u1.y : u1.x) + bv.y;
            o.z = (hi ? u2.y : u2.x) + bv.z;
            o.w = (hi ? u3.y : u3.x) + bv.w;
            ((float4*)g_h2)[(size_t)gr * 16 + tx] = o;
            ps[0] += o.x; pss[0] += o.x * o.x;
            ps[1] += o.y; pss[1] += o.y * o.y;
            ps[2] += o.z; pss[2] += o.z * o.z;
            ps[3] += o.w; pss[3] += o.w * o.w;
        }
    }
    #pragma unroll
    for (int j = 0; j < 4; j++) {
        atomicAdd(&cs[tx * 4 + j], ps[j]);
        atomicAdd(&css[tx * 4 + j], pss[j]);
    }
    __syncthreads();
    if (tid < DIM) {
        atomicAdd(&g_sum[tid], cs[tid]);
        atomicAdd(&g_sumsq[tid], css[tid]);
    }
}

// ---------------------------------------------------------------------------
// 5) BN finalize
// ---------------------------------------------------------------------------
__global__ void bn_finalize_kernel(const float* __restrict__ gamma,
                                   const float* __restrict__ beta, int n) {
    int c = threadIdx.x;
    if (c < DIM) {
        float inv_n = 1.0f / (float)n;
        float mean = g_sum[c] * inv_n;
        float var = g_sumsq[c] * inv_n - mean * mean;
        float inv = rsqrtf(var + EPS);
        float sc = inv * gamma[c];
        g_scale[c] = sc;
        g_shift[c] = beta[c] - mean * sc;
    }
}

// ---------------------------------------------------------------------------
// 6) out = x + relu(h2*scale + shift)
// ---------------------------------------------------------------------------
__global__ void final_kernel(const float4* __restrict__ x4,
                             float4* __restrict__ out4, int n16) {
    int i = blockIdx.x * blockDim.x + threadIdx.x;
    if (i >= n16) return;
    int c = (i & 15) * 4;
    float4 h = ((const float4*)g_h2)[i];
    float4 xv = __ldg(x4 + i);
    float4 o;
    o.x = xv.x + fmaxf(h.x * g_scale[c + 0] + g_shift[c + 0], 0.f);
    o.y = xv.y + fmaxf(h.y * g_scale[c + 1] + g_shift[c + 1], 0.f);
    o.z = xv.z + fmaxf(h.z * g_scale[c + 2] + g_shift[c + 2], 0.f);
    o.w = xv.w + fmaxf(h.w * g_scale[c + 3] + g_shift[c + 3], 0.f);
    out4[i] = o;
}

// ---------------------------------------------------------------------------
extern "C" void kernel_launch(void* const* d_in, const int* in_sizes, int n_in,
                              void* d_out, int out_size) {
    const float* x     = (const float*)d_in[0];
    const int*   src   = (const int*)d_in[1];
    const int*   dst   = (const int*)d_in[2];
    const float* W     = (const float*)d_in[3];
    const float* b     = (const float*)d_in[4];
    const float* gamma = (const float*)d_in[5];
    const float* beta  = (const float*)d_in[6];

    int n = in_sizes[0] / DIM;   // 100000
    int e = in_sizes[1];         // 1600000

    void *p_do, *p_di;
    cudaGetSymbolAddress(&p_do, g_deg_out);
    cudaGetSymbolAddress(&p_di, g_deg_in);
    cudaMemsetAsync(p_do, 0, (size_t)n * sizeof(int));
    cudaMemsetAsync(p_di, 0, (size_t)n * sizeof(int));

    int e4 = e / 4;
    deg_kernel<<<(e4 + 255) / 256, 256>>>((const int4*)src, (const int4*)dst, e4);

    int nb = (n + SCAN_B - 1) / SCAN_B;
    scanA_kernel<<<nb, SCAN_B>>>(n);
    scanB_kernel<<<1, SCAN_B>>>(nb);
    scanC_kernel<<<(n + 255) / 256, 256>>>(n);

    fill_kernel<<<(e4 + 255) / 256, 256>>>((const int4*)src, (const int4*)dst, e4);

    int smem = DIM * DIM * 8 + DIM * ASTRIDE * 4 + 2 * DIM * 4;  // ~51.2KB
    cudaFuncSetAttribute(fused_kernel, cudaFuncAttributeMaxDynamicSharedMemorySize, smem);
    fused_kernel<<<(n + 63) / 64, 256, smem>>>((const float4*)x, W, b, n);

    bn_finalize_kernel<<<1, 64>>>(gamma, beta, n);
    final_kernel<<<(n * 16 + 255) / 256, 256>>>((const float4*)x, (float4*)d_out, n * 16);
}

// round 4
// speedup vs baseline: 1.1121x; 1.1121x over previous
#include <cuda_runtime.h>
#include <cuda_fp16.h>

#define N_NODES 100000
#define N_EDGES 1600000
#define DIM 64
#define EPS 1e-5f
#define SCAN_B 512
#define ASTRIDE 68   // padded row length (floats) for k-major A tile

typedef unsigned long long ull;

// ---- scratch (device globals; no allocation allowed) ----
__device__ __align__(16) float  g_agg[N_NODES * DIM];   // gathered features (fp32)
__device__ __align__(16) float  g_h2[N_NODES * DIM];    // post-GEMM activations
__device__ __align__(16) __half g_xh[N_NODES * DIM];    // fp16 prescaled x
__device__ int   g_deg_out[N_NODES];
__device__ int   g_deg_in[N_NODES];
__device__ int   g_off[N_NODES];
__device__ int   g_fill[N_NODES];
__device__ int   g_csr[N_EDGES];
__device__ int   g_bsum[SCAN_B];
__device__ int   g_boff[SCAN_B];
__device__ float g_norm_src[N_NODES];
__device__ float g_sum[DIM];
__device__ float g_sumsq[DIM];
__device__ float g_scale[DIM];
__device__ float g_shift[DIM];

__device__ __forceinline__ void ffma2(ull& d, ull a, ull b) {
    asm("fma.rn.f32x2 %0, %1, %2, %0;" : "+l"(d) : "l"(a), "l"(b));
}
__device__ __forceinline__ float2 unpack2(ull v) {
    float2 r;
    asm("mov.b64 {%0, %1}, %2;" : "=f"(r.x), "=f"(r.y) : "l"(v));
    return r;
}

// ---------------------------------------------------------------------------
// 1) degree histogram (both directions), 4 edges per thread via int4
// ---------------------------------------------------------------------------
__global__ void deg_kernel(const int4* __restrict__ src4,
                           const int4* __restrict__ dst4, int e4) {
    int i = blockIdx.x * blockDim.x + threadIdx.x;
    if (i < e4) {
        int4 s = __ldg(src4 + i);
        int4 d = __ldg(dst4 + i);
        atomicAdd(&g_deg_out[s.x], 1); atomicAdd(&g_deg_out[s.y], 1);
        atomicAdd(&g_deg_out[s.z], 1); atomicAdd(&g_deg_out[s.w], 1);
        atomicAdd(&g_deg_in[d.x], 1);  atomicAdd(&g_deg_in[d.y], 1);
        atomicAdd(&g_deg_in[d.z], 1);  atomicAdd(&g_deg_in[d.w], 1);
    }
}

// ---------------------------------------------------------------------------
// 2a) per-block exclusive scan of deg_in
// ---------------------------------------------------------------------------
__global__ void scanA_kernel(int n) {
    __shared__ int sm[SCAN_B];
    int t = threadIdx.x;
    int i = blockIdx.x * SCAN_B + t;
    int v = (i < n) ? g_deg_in[i] : 0;
    sm[t] = v;
    __syncthreads();
    #pragma unroll
    for (int off = 1; off < SCAN_B; off <<= 1) {
        int a = (t >= off) ? sm[t - off] : 0;
        __syncthreads();
        sm[t] += a;
        __syncthreads();
    }
    if (i < n) g_off[i] = sm[t] - v;
    if (t == SCAN_B - 1) g_bsum[blockIdx.x] = sm[t];
}

// ---------------------------------------------------------------------------
// 2b) scan of block sums; also zero BN accumulators
// ---------------------------------------------------------------------------
__global__ void scanB_kernel(int nb) {
    __shared__ int sm[SCAN_B];
    int t = threadIdx.x;
    int v = (t < nb) ? g_bsum[t] : 0;
    sm[t] = v;
    __syncthreads();
    #pragma unroll
    for (int off = 1; off < SCAN_B; off <<= 1) {
        int a = (t >= off) ? sm[t - off] : 0;
        __syncthreads();
        sm[t] += a;
        __syncthreads();
    }
    if (t < nb) g_boff[t] = sm[t] - v;
    if (t < DIM) { g_sum[t] = 0.f; g_sumsq[t] = 0.f; }
}

// ---------------------------------------------------------------------------
// 2c) finalize offsets + fill cursors + norm_src
// ---------------------------------------------------------------------------
__global__ void scanC_kernel(int n) {
    int i = blockIdx.x * blockDim.x + threadIdx.x;
    if (i < n) {
        int off = g_off[i] + g_boff[i >> 9];
        g_off[i] = off;
        g_fill[i] = off;
        int d = g_deg_out[i];
        g_norm_src[i] = rsqrtf((float)(d < 1 ? 1 : d));
    }
}

// ---------------------------------------------------------------------------
// 3) CSR bucket fill (4 edges/thread)
// ---------------------------------------------------------------------------
__global__ void fill_kernel(const int4* __restrict__ src4,
                            const int4* __restrict__ dst4, int e4) {
    int i = blockIdx.x * blockDim.x + threadIdx.x;
    if (i < e4) {
        int4 s = __ldg(src4 + i);
        int4 d = __ldg(dst4 + i);
        g_csr[atomicAdd(&g_fill[d.x], 1)] = s.x;
        g_csr[atomicAdd(&g_fill[d.y], 1)] = s.y;
        g_csr[atomicAdd(&g_fill[d.z], 1)] = s.z;
        g_csr[atomicAdd(&g_fill[d.w], 1)] = s.w;
    }
}

// ---------------------------------------------------------------------------
// 4) prescale: xh = fp16(x * norm_src), 4 cols per thread
// ---------------------------------------------------------------------------
__global__ void prescale_kernel(const float4* __restrict__ x4, int n16) {
    int i = blockIdx.x * blockDim.x + threadIdx.x;
    if (i >= n16) return;
    float ns = __ldg(&g_norm_src[i >> 4]);
    float4 v = __ldg(x4 + i);
    __half2 h0 = __floats2half2_rn(v.x * ns, v.y * ns);
    __half2 h1 = __floats2half2_rn(v.z * ns, v.w * ns);
    ((__half2*)g_xh)[i * 2 + 0] = h0;
    ((__half2*)g_xh)[i * 2 + 1] = h1;
}

// ---------------------------------------------------------------------------
// 5) gather: agg[v] = norm_dst[v] * sum_{s in in(v)} xh[s]
//    16 lanes per node, lane c reads 4 halves (8 B) per edge.
// ---------------------------------------------------------------------------
__global__ void gather_kernel(int n) {
    int tid = threadIdx.x;
    int node = blockIdx.x * 16 + (tid >> 4);
    if (node >= n) return;
    int c = tid & 15;
    int start = g_off[node];
    int deg = g_deg_in[node];
    const __half2* xh2 = (const __half2*)g_xh;

    float4 acc = make_float4(0.f, 0.f, 0.f, 0.f);
    int j = 0;
    for (; j + 1 < deg; j += 2) {
        int s0 = __ldg(&g_csr[start + j]);
        int s1 = __ldg(&g_csr[start + j + 1]);
        __half2 a0 = __ldg(xh2 + (size_t)s0 * 32 + c * 2);
        __half2 b0 = __ldg(xh2 + (size_t)s0 * 32 + c * 2 + 1);
        __half2 a1 = __ldg(xh2 + (size_t)s1 * 32 + c * 2);
        __half2 b1 = __ldg(xh2 + (size_t)s1 * 32 + c * 2 + 1);
        float2 f0 = __half22float2(a0), f1 = __half22float2(b0);
        float2 f2 = __half22float2(a1), f3 = __half22float2(b1);
        acc.x += f0.x + f2.x; acc.y += f0.y + f2.y;
        acc.z += f1.x + f3.x; acc.w += f1.y + f3.y;
    }
    if (j < deg) {
        int s = __ldg(&g_csr[start + j]);
        __half2 a = __ldg(xh2 + (size_t)s * 32 + c * 2);
        __half2 b = __ldg(xh2 + (size_t)s * 32 + c * 2 + 1);
        float2 f0 = __half22float2(a), f1 = __half22float2(b);
        acc.x += f0.x; acc.y += f0.y; acc.z += f1.x; acc.w += f1.y;
    }
    float nd = rsqrtf((float)(deg < 1 ? 1 : deg));
    acc.x *= nd; acc.y *= nd; acc.z *= nd; acc.w *= nd;
    ((float4*)g_agg)[(size_t)node * 16 + c] = acc;
}

// ---------------------------------------------------------------------------
// 6) GEMM: h2 = agg @ W + b via f32x2, fused BN stats (R3 Phase B, standalone)
// ---------------------------------------------------------------------------
__global__ void __launch_bounds__(256)
gemm_bn_kernel(const float* __restrict__ W,
               const float* __restrict__ b, int n) {
    extern __shared__ char smraw[];
    ull*   Wdup = (ull*)smraw;                       // [DIM][DIM] f32x2 {w,w}
    float* Asm2 = (float*)(smraw + DIM * DIM * 8);   // [DIM k][ASTRIDE rows]
    float* cs   = (float*)(smraw + DIM * DIM * 8 + DIM * ASTRIDE * 4);
    float* css  = cs + DIM;

    int tid = threadIdx.x;
    int r0 = blockIdx.x * 64;

    #pragma unroll
    for (int j = 0; j < 16; j++) {
        int i = tid + j * 256;
        float w = __ldg(W + i);
        ((float2*)Wdup)[i] = make_float2(w, w);
    }
    if (tid < DIM) { cs[tid] = 0.f; css[tid] = 0.f; }

    // load A tile (k-major) from g_agg
    #pragma unroll
    for (int j = 0; j < 4; j++) {
        int i = tid + j * 256;
        int row = i >> 4;
        int c = i & 15;
        int gr = r0 + row;
        float4 v = make_float4(0.f, 0.f, 0.f, 0.f);
        if (gr < n) v = ((const float4*)g_agg)[(size_t)gr * 16 + c];
        Asm2[(4 * c + 0) * ASTRIDE + row] = v.x;
        Asm2[(4 * c + 1) * ASTRIDE + row] = v.y;
        Asm2[(4 * c + 2) * ASTRIDE + row] = v.z;
        Asm2[(4 * c + 3) * ASTRIDE + row] = v.w;
    }
    __syncthreads();

    int tx = tid & 15;
    int ty = tid >> 4;
    ull acc2[2][4] = {};   // [row-pair][col]

    #pragma unroll 4
    for (int k = 0; k < DIM; k++) {
        ulonglong2 av = *(const ulonglong2*)&Asm2[k * ASTRIDE + ty * 4];
        ulonglong2 wA = *(const ulonglong2*)&Wdup[k * DIM + tx * 4];
        ulonglong2 wB = *(const ulonglong2*)&Wdup[k * DIM + tx * 4 + 2];
        ffma2(acc2[0][0], av.x, wA.x); ffma2(acc2[1][0], av.y, wA.x);
        ffma2(acc2[0][1], av.x, wA.y); ffma2(acc2[1][1], av.y, wA.y);
        ffma2(acc2[0][2], av.x, wB.x); ffma2(acc2[1][2], av.y, wB.x);
        ffma2(acc2[0][3], av.x, wB.y); ffma2(acc2[1][3], av.y, wB.y);
    }

    float4 bv = ((const float4*)b)[tx];
    float ps[4] = {0.f, 0.f, 0.f, 0.f};
    float pss[4] = {0.f, 0.f, 0.f, 0.f};
    #pragma unroll
    for (int i = 0; i < 4; i++) {
        int gr = r0 + ty * 4 + i;
        if (gr < n) {
            int p = i >> 1, hi = i & 1;
            float2 u0 = unpack2(acc2[p][0]);
            float2 u1 = unpack2(acc2[p][1]);
            float2 u2 = unpack2(acc2[p][2]);
            float2 u3 = unpack2(acc2[p][3]);
            float4 o;
            o.x = (hi ? u0.y : u0.x) + bv.x;
            o.y = (hi ? u1.y : u1.x) + bv.y;
            o.z = (hi ? u2.y : u2.x) + bv.z;
            o.w = (hi ? u3.y : u3.x) + bv.w;
            ((float4*)g_h2)[(size_t)gr * 16 + tx] = o;
            ps[0] += o.x; pss[0] += o.x * o.x;
            ps[1] += o.y; pss[1] += o.y * o.y;
            ps[2] += o.z; pss[2] += o.z * o.z;
            ps[3] += o.w; pss[3] += o.w * o.w;
        }
    }
    #pragma unroll
    for (int j = 0; j < 4; j++) {
        atomicAdd(&cs[tx * 4 + j], ps[j]);
        atomicAdd(&css[tx * 4 + j], pss[j]);
    }
    __syncthreads();
    if (tid < DIM) {
        atomicAdd(&g_sum[tid], cs[tid]);
        atomicAdd(&g_sumsq[tid], css[tid]);
    }
}

// ---------------------------------------------------------------------------
// 7) BN finalize
// ---------------------------------------------------------------------------
__global__ void bn_finalize_kernel(const float* __restrict__ gamma,
                                   const float* __restrict__ beta, int n) {
    int c = threadIdx.x;
    if (c < DIM) {
        float inv_n = 1.0f / (float)n;
        float mean = g_sum[c] * inv_n;
        float var = g_sumsq[c] * inv_n - mean * mean;
        float inv = rsqrtf(var + EPS);
        float sc = inv * gamma[c];
        g_scale[c] = sc;
        g_shift[c] = beta[c] - mean * sc;
    }
}

// ---------------------------------------------------------------------------
// 8) out = x + relu(h2*scale + shift)
// ---------------------------------------------------------------------------
__global__ void final_kernel(const float4* __restrict__ x4,
                             float4* __restrict__ out4, int n16) {
    int i = blockIdx.x * blockDim.x + threadIdx.x;
    if (i >= n16) return;
    int c = (i & 15) * 4;
    float4 h = ((const float4*)g_h2)[i];
    float4 xv = __ldg(x4 + i);
    float4 o;
    o.x = xv.x + fmaxf(h.x * g_scale[c + 0] + g_shift[c + 0], 0.f);
    o.y = xv.y + fmaxf(h.y * g_scale[c + 1] + g_shift[c + 1], 0.f);
    o.z = xv.z + fmaxf(h.z * g_scale[c + 2] + g_shift[c + 2], 0.f);
    o.w = xv.w + fmaxf(h.w * g_scale[c + 3] + g_shift[c + 3], 0.f);
    out4[i] = o;
}

// ---------------------------------------------------------------------------
extern "C" void kernel_launch(void* const* d_in, const int* in_sizes, int n_in,
                              void* d_out, int out_size) {
    const float* x     = (const float*)d_in[0];
    const int*   src   = (const int*)d_in[1];
    const int*   dst   = (const int*)d_in[2];
    const float* W     = (const float*)d_in[3];
    const float* b     = (const float*)d_in[4];
    const float* gamma = (const float*)d_in[5];
    const float* beta  = (const float*)d_in[6];

    int n = in_sizes[0] / DIM;   // 100000
    int e = in_sizes[1];         // 1600000

    void *p_do, *p_di;
    cudaGetSymbolAddress(&p_do, g_deg_out);
    cudaGetSymbolAddress(&p_di, g_deg_in);
    cudaMemsetAsync(p_do, 0, (size_t)n * sizeof(int));
    cudaMemsetAsync(p_di, 0, (size_t)n * sizeof(int));

    int e4 = e / 4;
    deg_kernel<<<(e4 + 255) / 256, 256>>>((const int4*)src, (const int4*)dst, e4);

    int nb = (n + SCAN_B - 1) / SCAN_B;
    scanA_kernel<<<nb, SCAN_B>>>(n);
    scanB_kernel<<<1, SCAN_B>>>(nb);
    scanC_kernel<<<(n + 255) / 256, 256>>>(n);

    fill_kernel<<<(e4 + 255) / 256, 256>>>((const int4*)src, (const int4*)dst, e4);
    prescale_kernel<<<(n * 16 + 255) / 256, 256>>>((const float4*)x, n * 16);

    gather_kernel<<<(n + 15) / 16, 256>>>(n);

    int smem = DIM * DIM * 8 + DIM * ASTRIDE * 4 + 2 * DIM * 4;
    cudaFuncSetAttribute(gemm_bn_kernel, cudaFuncAttributeMaxDynamicSharedMemorySize, smem);
    gemm_bn_kernel<<<(n + 63) / 64, 256, smem>>>(W, b, n);

    bn_finalize_kernel<<<1, 64>>>(gamma, beta, n);
    final_kernel<<<(n * 16 + 255) / 256, 256>>>((const float4*)x, (float4*)d_out, n * 16);
}

// round 5
// speedup vs baseline: 1.4786x; 1.3295x over previous
#include <cuda_runtime.h>
#include <cuda_fp16.h>

#define N_NODES 100000
#define N_EDGES 1600000
#define DIM 64
#define EPS 1e-5f
#define SCAN_B 512

// ---- scratch (device globals; zero-initialized at module load) ----
__device__ __align__(16) float  g_agg[N_NODES * DIM];   // gathered features (fp32)
__device__ __align__(16) float  g_h2[N_NODES * DIM];    // post-GEMM activations
__device__ __align__(16) __half g_xh[N_NODES * DIM];    // fp16 prescaled x
__device__ int   g_deg_out[N_NODES];   // zeroed at end of final_kernel
__device__ int   g_deg_in[N_NODES];    // zeroed at end of final_kernel
__device__ int   g_off[N_NODES];       // CSR offsets; after fill: end offsets
__device__ int   g_csr[N_EDGES];
__device__ int   g_bsum[SCAN_B];
__device__ int   g_boff[SCAN_B];
__device__ float g_sum[DIM];
__device__ float g_sumsq[DIM];
__device__ float g_scale[DIM];
__device__ float g_shift[DIM];

// ---------------------------------------------------------------------------
// 1) degree histogram (both directions), 4 edges per thread via int4
// ---------------------------------------------------------------------------
__global__ void deg_kernel(const int4* __restrict__ src4,
                           const int4* __restrict__ dst4, int e4) {
    int i = blockIdx.x * blockDim.x + threadIdx.x;
    if (i < e4) {
        int4 s = __ldg(src4 + i);
        int4 d = __ldg(dst4 + i);
        atomicAdd(&g_deg_out[s.x], 1); atomicAdd(&g_deg_out[s.y], 1);
        atomicAdd(&g_deg_out[s.z], 1); atomicAdd(&g_deg_out[s.w], 1);
        atomicAdd(&g_deg_in[d.x], 1);  atomicAdd(&g_deg_in[d.y], 1);
        atomicAdd(&g_deg_in[d.z], 1);  atomicAdd(&g_deg_in[d.w], 1);
    }
}

// ---------------------------------------------------------------------------
// 2a) per-block exclusive scan of deg_in
// ---------------------------------------------------------------------------
__global__ void scanA_kernel(int n) {
    __shared__ int sm[SCAN_B];
    int t = threadIdx.x;
    int i = blockIdx.x * SCAN_B + t;
    int v = (i < n) ? g_deg_in[i] : 0;
    sm[t] = v;
    __syncthreads();
    #pragma unroll
    for (int off = 1; off < SCAN_B; off <<= 1) {
        int a = (t >= off) ? sm[t - off] : 0;
        __syncthreads();
        sm[t] += a;
        __syncthreads();
    }
    if (i < n) g_off[i] = sm[t] - v;
    if (t == SCAN_B - 1) g_bsum[blockIdx.x] = sm[t];
}

// ---------------------------------------------------------------------------
// 2b) scan of block sums; also zero BN accumulators
// ---------------------------------------------------------------------------
__global__ void scanB_kernel(int nb) {
    __shared__ int sm[SCAN_B];
    int t = threadIdx.x;
    int v = (t < nb) ? g_bsum[t] : 0;
    sm[t] = v;
    __syncthreads();
    #pragma unroll
    for (int off = 1; off < SCAN_B; off <<= 1) {
        int a = (t >= off) ? sm[t - off] : 0;
        __syncthreads();
        sm[t] += a;
        __syncthreads();
    }
    if (t < nb) g_boff[t] = sm[t] - v;
    if (t < DIM) { g_sum[t] = 0.f; g_sumsq[t] = 0.f; }
}

// ---------------------------------------------------------------------------
// 2c) prep: finalize offsets + prescale xh = fp16(x * norm_src)
//     16 threads per node (one per float4 column chunk).
// ---------------------------------------------------------------------------
__global__ void prep_kernel(const float4* __restrict__ x4, int n16) {
    int i = blockIdx.x * blockDim.x + threadIdx.x;
    if (i >= n16) return;
    int node = i >> 4;
    int c = i & 15;
    if (c == 0) g_off[node] += g_boff[node >> 9];  // finalize exclusive offset
    int d = __ldg(&g_deg_out[node]);
    float ns = rsqrtf((float)(d < 1 ? 1 : d));
    float4 v = __ldg(x4 + i);
    __half2 h0 = __floats2half2_rn(v.x * ns, v.y * ns);
    __half2 h1 = __floats2half2_rn(v.z * ns, v.w * ns);
    ((__half2*)g_xh)[i * 2 + 0] = h0;
    ((__half2*)g_xh)[i * 2 + 1] = h1;
}

// ---------------------------------------------------------------------------
// 3) CSR bucket fill: bumps g_off (afterwards g_off[i] = end offset of row i)
// ---------------------------------------------------------------------------
__global__ void fill_kernel(const int4* __restrict__ src4,
                            const int4* __restrict__ dst4, int e4) {
    int i = blockIdx.x * blockDim.x + threadIdx.x;
    if (i < e4) {
        int4 s = __ldg(src4 + i);
        int4 d = __ldg(dst4 + i);
        g_csr[atomicAdd(&g_off[d.x], 1)] = s.x;
        g_csr[atomicAdd(&g_off[d.y], 1)] = s.y;
        g_csr[atomicAdd(&g_off[d.z], 1)] = s.z;
        g_csr[atomicAdd(&g_off[d.w], 1)] = s.w;
    }
}

// ---------------------------------------------------------------------------
// 4) gather: agg[v] = norm_dst[v] * sum_{s in in(v)} xh[s]
//    8 lanes per node, lane c reads one uint4 (8 halves, 16B) per edge.
// ---------------------------------------------------------------------------
__global__ void gather_kernel(int n) {
    int tid = threadIdx.x;
    int node = blockIdx.x * 32 + (tid >> 3);
    if (node >= n) return;
    int c = tid & 7;
    int deg = __ldg(&g_deg_in[node]);
    int start = __ldg(&g_off[node]) - deg;   // off was bumped to end by fill
    const uint4* xr = (const uint4*)g_xh;    // row = 8 uint4

    float2 a0 = {0.f, 0.f}, a1 = {0.f, 0.f}, a2 = {0.f, 0.f}, a3 = {0.f, 0.f};
    int j = 0;
    for (; j + 1 < deg; j += 2) {
        int s0 = __ldg(&g_csr[start + j]);
        int s1 = __ldg(&g_csr[start + j + 1]);
        uint4 v0 = __ldg(xr + (size_t)s0 * 8 + c);
        uint4 v1 = __ldg(xr + (size_t)s1 * 8 + c);
        float2 f;
        f = __half22float2(*(__half2*)&v0.x); a0.x += f.x; a0.y += f.y;
        f = __half22float2(*(__half2*)&v0.y); a1.x += f.x; a1.y += f.y;
        f = __half22float2(*(__half2*)&v0.z); a2.x += f.x; a2.y += f.y;
        f = __half22float2(*(__half2*)&v0.w); a3.x += f.x; a3.y += f.y;
        f = __half22float2(*(__half2*)&v1.x); a0.x += f.x; a0.y += f.y;
        f = __half22float2(*(__half2*)&v1.y); a1.x += f.x; a1.y += f.y;
        f = __half22float2(*(__half2*)&v1.z); a2.x += f.x; a2.y += f.y;
        f = __half22float2(*(__half2*)&v1.w); a3.x += f.x; a3.y += f.y;
    }
    if (j < deg) {
        int s = __ldg(&g_csr[start + j]);
        uint4 v = __ldg(xr + (size_t)s * 8 + c);
        float2 f;
        f = __half22float2(*(__half2*)&v.x); a0.x += f.x; a0.y += f.y;
        f = __half22float2(*(__half2*)&v.y); a1.x += f.x; a1.y += f.y;
        f = __half22float2(*(__half2*)&v.z); a2.x += f.x; a2.y += f.y;
        f = __half22float2(*(__half2*)&v.w); a3.x += f.x; a3.y += f.y;
    }
    float nd = rsqrtf((float)(deg < 1 ? 1 : deg));
    float4 o0 = make_float4(a0.x * nd, a0.y * nd, a1.x * nd, a1.y * nd);
    float4 o1 = make_float4(a2.x * nd, a2.y * nd, a3.x * nd, a3.y * nd);
    ((float4*)g_agg)[(size_t)node * 16 + c * 2 + 0] = o0;
    ((float4*)g_agg)[(size_t)node * 16 + c * 2 + 1] = o1;
}

// ---------------------------------------------------------------------------
// 5) GEMM: h2 = agg @ W + b, fused BN stats (R2-proven version)
// ---------------------------------------------------------------------------
__global__ void gemm_bn_kernel(const float* __restrict__ W,
                               const float* __restrict__ b, int n) {
    __shared__ float Wsm[DIM * DIM];      // [k][j], row-major
    __shared__ float Asm[DIM][DIM + 1];   // [row][k], padded
    __shared__ float cs[DIM];
    __shared__ float css[DIM];

    int tid = threadIdx.x;
    int r0 = blockIdx.x * 64;

    #pragma unroll
    for (int j = 0; j < 4; j++) {
        int i = tid + j * 256;
        ((float4*)Wsm)[i] = ((const float4*)W)[i];
    }
    #pragma unroll
    for (int j = 0; j < 4; j++) {
        int i = tid + j * 256;
        int row = i >> 4;
        int c = i & 15;
        int gr = r0 + row;
        float4 v = make_float4(0.f, 0.f, 0.f, 0.f);
        if (gr < n) v = ((const float4*)g_agg)[(size_t)gr * 16 + c];
        float* dp = &Asm[row][c * 4];
        dp[0] = v.x; dp[1] = v.y; dp[2] = v.z; dp[3] = v.w;
    }
    if (tid < DIM) { cs[tid] = 0.f; css[tid] = 0.f; }
    __syncthreads();

    int tx = tid & 15;
    int ty = tid >> 4;
    float acc[4][4] = {};

    #pragma unroll 8
    for (int k = 0; k < DIM; k++) {
        float4 w = ((const float4*)Wsm)[k * 16 + tx];
        float a0 = Asm[ty * 4 + 0][k];
        float a1 = Asm[ty * 4 + 1][k];
        float a2 = Asm[ty * 4 + 2][k];
        float a3 = Asm[ty * 4 + 3][k];
        acc[0][0] += a0 * w.x; acc[0][1] += a0 * w.y; acc[0][2] += a0 * w.z; acc[0][3] += a0 * w.w;
        acc[1][0] += a1 * w.x; acc[1][1] += a1 * w.y; acc[1][2] += a1 * w.z; acc[1][3] += a1 * w.w;
        acc[2][0] += a2 * w.x; acc[2][1] += a2 * w.y; acc[2][2] += a2 * w.z; acc[2][3] += a2 * w.w;
        acc[3][0] += a3 * w.x; acc[3][1] += a3 * w.y; acc[3][2] += a3 * w.z; acc[3][3] += a3 * w.w;
    }

    float4 bv = ((const float4*)b)[tx];
    float ps[4] = {0.f, 0.f, 0.f, 0.f};
    float pss[4] = {0.f, 0.f, 0.f, 0.f};
    #pragma unroll
    for (int i = 0; i < 4; i++) {
        int gr = r0 + ty * 4 + i;
        if (gr < n) {
            float4 o;
            o.x = acc[i][0] + bv.x;
            o.y = acc[i][1] + bv.y;
            o.z = acc[i][2] + bv.z;
            o.w = acc[i][3] + bv.w;
            ((float4*)g_h2)[(size_t)gr * 16 + tx] = o;
            ps[0] += o.x; pss[0] += o.x * o.x;
            ps[1] += o.y; pss[1] += o.y * o.y;
            ps[2] += o.z; pss[2] += o.z * o.z;
            ps[3] += o.w; pss[3] += o.w * o.w;
        }
    }
    #pragma unroll
    for (int j = 0; j < 4; j++) {
        atomicAdd(&cs[tx * 4 + j], ps[j]);
        atomicAdd(&css[tx * 4 + j], pss[j]);
    }
    __syncthreads();
    if (tid < DIM) {
        atomicAdd(&g_sum[tid], cs[tid]);
        atomicAdd(&g_sumsq[tid], css[tid]);
    }
}

// ---------------------------------------------------------------------------
// 6) BN finalize
// ---------------------------------------------------------------------------
__global__ void bn_finalize_kernel(const float* __restrict__ gamma,
                                   const float* __restrict__ beta, int n) {
    int c = threadIdx.x;
    if (c < DIM) {
        float inv_n = 1.0f / (float)n;
        float mean = g_sum[c] * inv_n;
        float var = g_sumsq[c] * inv_n - mean * mean;
        float inv = rsqrtf(var + EPS);
        float sc = inv * gamma[c];
        g_scale[c] = sc;
        g_shift[c] = beta[c] - mean * sc;
    }
}

// ---------------------------------------------------------------------------
// 7) out = x + relu(h2*scale + shift); tail re-zeroes degree arrays for the
//    next invocation (globals start zero-initialized at module load, so the
//    invariant "deg arrays are zero at kernel_launch entry" holds every call).
// ---------------------------------------------------------------------------
__global__ void final_kernel(const float4* __restrict__ x4,
                             float4* __restrict__ out4, int n16) {
    int i = blockIdx.x * blockDim.x + threadIdx.x;
    if (i >= n16) return;
    int c = (i & 15) * 4;
    float4 h = ((const float4*)g_h2)[i];
    float4 xv = __ldg(x4 + i);
    float4 o;
    o.x = xv.x + fmaxf(h.x * g_scale[c + 0] + g_shift[c + 0], 0.f);
    o.y = xv.y + fmaxf(h.y * g_scale[c + 1] + g_shift[c + 1], 0.f);
    o.z = xv.z + fmaxf(h.z * g_scale[c + 2] + g_shift[c + 2], 0.f);
    o.w = xv.w + fmaxf(h.w * g_scale[c + 3] + g_shift[c + 3], 0.f);
    out4[i] = o;
    int node = i >> 4;
    if ((i & 15) == 0) {            // one thread per node zeroes both counters
        g_deg_out[node] = 0;
        g_deg_in[node] = 0;
    }
}

// ---------------------------------------------------------------------------
extern "C" void kernel_launch(void* const* d_in, const int* in_sizes, int n_in,
                              void* d_out, int out_size) {
    const float* x     = (const float*)d_in[0];
    const int*   src   = (const int*)d_in[1];
    const int*   dst   = (const int*)d_in[2];
    const float* W     = (const float*)d_in[3];
    const float* b     = (const float*)d_in[4];
    const float* gamma = (const float*)d_in[5];
    const float* beta  = (const float*)d_in[6];

    int n = in_sizes[0] / DIM;   // 100000
    int e = in_sizes[1];         // 1600000
    int e4 = e / 4;
    int nb = (n + SCAN_B - 1) / SCAN_B;

    deg_kernel<<<(e4 + 255) / 256, 256>>>((const int4*)src, (const int4*)dst, e4);
    scanA_kernel<<<nb, SCAN_B>>>(n);
    scanB_kernel<<<1, SCAN_B>>>(nb);
    prep_kernel<<<(n * 16 + 255) / 256, 256>>>((const float4*)x, n * 16);
    fill_kernel<<<(e4 + 255) / 256, 256>>>((const int4*)src, (const int4*)dst, e4);
    gather_kernel<<<(n + 31) / 32, 256>>>(n);
    gemm_bn_kernel<<<(n + 63) / 64, 256>>>(W, b, n);
    bn_finalize_kernel<<<1, 64>>>(gamma, beta, n);
    final_kernel<<<(n * 16 + 255) / 256, 256>>>((const float4*)x, (float4*)d_out, n * 16);
}